// round 15
// baseline (speedup 1.0000x reference)
#include <cuda_runtime.h>
#include <cuda_fp16.h>
#include <cstdint>
#include <cstddef>

// Problem constants
constexpr int B  = 16;
constexpr int T  = 448;
constexpr int J  = 448;
constexpr int C  = 1024;
constexpr int H  = 16;
constexpr int HD = 64;
constexpr int ROWS = B * T;          // 7168 (== B*J)
constexpr size_t C2 = (size_t)C * C;

// ---------------------------------------------------------------------------
// Scratch (static device globals; no allocation allowed)
// ---------------------------------------------------------------------------
__device__ __half g_ln1[(size_t)ROWS * C];                // ln1 / ln2(out) (origin)
__device__ __half g_ln2[(size_t)ROWS * C];                // ln2(src) (branch A)
__device__ __half g_ln3[(size_t)ROWS * C];                // ln3 (branch B)
__device__ __half g_o  [(size_t)ROWS * C];                // flash out (origin)
__device__ __half g_hid[(size_t)ROWS * 4 * C];            // ffn hidden (branch B)
__device__ __half g_wt [16 * C2];                         // weights fp16 [N,K]
__device__ __half g_x1 [(size_t)ROWS * 3 * C];            // qkv fp16 out (origin)
__device__ __half g_x2 [(size_t)ROWS * 2 * C];            // kv fp16 out (branch A)
__device__ __half g_x3 [(size_t)ROWS * C];                // q2 fp16 out (origin)

// ---------------------------------------------------------------------------
// PTX helpers (family-agnostic: legal at compute_103)
// ---------------------------------------------------------------------------
__device__ __forceinline__ uint32_t smem_u32(const void* p) {
    uint32_t a;
    asm("{ .reg .u64 t; cvta.to.shared.u64 t, %1; cvt.u32.u64 %0, t; }"
        : "=r"(a) : "l"(p));
    return a;
}

__device__ __forceinline__ void ldsm4(uint32_t& r0, uint32_t& r1,
                                      uint32_t& r2, uint32_t& r3, uint32_t addr) {
    asm volatile("ldmatrix.sync.aligned.m8n8.x4.shared.b16 {%0,%1,%2,%3}, [%4];"
        : "=r"(r0), "=r"(r1), "=r"(r2), "=r"(r3) : "r"(addr));
}

__device__ __forceinline__ void ldsm4_t(uint32_t& r0, uint32_t& r1,
                                        uint32_t& r2, uint32_t& r3, uint32_t addr) {
    asm volatile("ldmatrix.sync.aligned.m8n8.x4.trans.shared.b16 {%0,%1,%2,%3}, [%4];"
        : "=r"(r0), "=r"(r1), "=r"(r2), "=r"(r3) : "r"(addr));
}

__device__ __forceinline__ void mma_f16(float* c, const uint32_t* a, const uint32_t* b) {
    asm volatile("mma.sync.aligned.m16n8k16.row.col.f32.f16.f16.f32 "
        "{%0,%1,%2,%3}, {%4,%5,%6,%7}, {%8,%9}, {%0,%1,%2,%3};"
        : "+f"(c[0]), "+f"(c[1]), "+f"(c[2]), "+f"(c[3])
        : "r"(a[0]), "r"(a[1]), "r"(a[2]), "r"(a[3]), "r"(b[0]), "r"(b[1]));
}

__device__ __forceinline__ uint32_t pack_f16x2(float a, float b) {
    uint32_t r;
    asm("cvt.rn.f16x2.f32 %0, %1, %2;" : "=r"(r) : "f"(b), "f"(a));
    return r;
}

__device__ __forceinline__ void cp16(uint32_t dst, const void* src) {
    asm volatile("cp.async.cg.shared.global [%0], [%1], 16;" :: "r"(dst), "l"(src));
}
__device__ __forceinline__ void cp_commit() {
    asm volatile("cp.async.commit_group;" ::: "memory");
}

// ---------------------------------------------------------------------------
// Weight transpose + fp32 -> fp16:  W[K,N] -> Wt[N,K]
// ---------------------------------------------------------------------------
__global__ __launch_bounds__(256) void wconv_kernel(
    const float* __restrict__ W, __half* __restrict__ Wt, int K, int N)
{
    __shared__ float t[32][33];
    int tx = threadIdx.x & 31, ty = threadIdx.x >> 5;
    int n0 = blockIdx.x * 32, k0 = blockIdx.y * 32;
    #pragma unroll
    for (int i = 0; i < 4; i++)
        t[ty + i * 8][tx] = W[(size_t)(k0 + ty + i * 8) * N + n0 + tx];
    __syncthreads();
    #pragma unroll
    for (int i = 0; i < 4; i++) {
        int n = ty + i * 8;
        Wt[(size_t)(n0 + n) * K + k0 + tx] = __float2half_rn(t[tx][n]);
    }
}

// ---------------------------------------------------------------------------
// HMMA GEMM, single-pass fp16, 2-stage cp.async pipeline (proven).
// A fp16 [M,K]; B fp16 [N,K]. Tile 128x128, BK=32, 256 threads.
// Output: fp32 Cf (+bias/res/relu) and/or fp16 Oh [M,N] (both coalesced).
// ---------------------------------------------------------------------------
constexpr int AST  = 40;                 // smem row stride (fp16 elems), 80B
constexpr int TBUF = 128 * AST;          // elems per tile

__global__ __launch_bounds__(256) void hmma_gemm(
    const __half* __restrict__ Ap, const __half* __restrict__ Bp,
    const float* __restrict__ bias, const float* __restrict__ res,
    float* __restrict__ Cf, __half* __restrict__ Oh,
    int M, int N, int K, int relu)
{
    __shared__ __half smbuf[2 * 2 * TBUF];   // 2 stages x {A,B} = 40 KB
    uint32_t sbase = smem_u32(smbuf);

    int tid = threadIdx.x, lane = tid & 31, w = tid >> 5;
    int wm = (w & 1) * 64, wn = (w >> 1) * 32;
    int m0 = blockIdx.y * 128, n0 = blockIdx.x * 128;

    float acc[4][4][4];
    #pragma unroll
    for (int i = 0; i < 4; i++)
        #pragma unroll
        for (int j = 0; j < 4; j++)
            #pragma unroll
            for (int r = 0; r < 4; r++) acc[i][j][r] = 0.f;

    const int nch = K >> 5;
    const int row = tid >> 2, seg = tid & 3;

    auto stage = [&](int kc, int s) {
        uint32_t base = sbase + (uint32_t)s * 2 * TBUF * 2;
        const size_t ka = (size_t)kc * 32;
        #pragma unroll
        for (int it = 0; it < 2; it++) {
            int r = row + it * 64;
            uint32_t so = (uint32_t)r * 80 + seg * 16;
            cp16(base + so,            Ap + (size_t)(m0 + r) * K + ka + seg * 8);
            cp16(base + TBUF * 2 + so, Bp + (size_t)(n0 + r) * K + ka + seg * 8);
        }
    };

    stage(0, 0);
    cp_commit();

    for (int kc = 0; kc < nch; kc++) {
        if (kc + 1 < nch) {
            stage(kc + 1, (kc + 1) & 1);
            cp_commit();
            asm volatile("cp.async.wait_group 1;" ::: "memory");
        } else {
            asm volatile("cp.async.wait_group 0;" ::: "memory");
        }
        __syncthreads();

        uint32_t base = sbase + (uint32_t)(kc & 1) * 2 * TBUF * 2;
        uint32_t bA = base, bB = base + TBUF * 2;

        #pragma unroll
        for (int ks = 0; ks < 2; ks++) {
            int arow = wm + (lane & 15);
            int akk  = ks * 16 + (lane >> 4) * 8;
            uint32_t aoff = (uint32_t)(arow * AST + akk) * 2;

            uint32_t a[4][4], bq[4][2];
            #pragma unroll
            for (int mi = 0; mi < 4; mi++)
                ldsm4(a[mi][0], a[mi][1], a[mi][2], a[mi][3],
                      bA + aoff + mi * 16 * AST * 2);
            int brow = wn + (lane & 15);
            uint32_t boff0 = (uint32_t)(brow * AST + akk) * 2;
            #pragma unroll
            for (int nb = 0; nb < 2; nb++) {
                uint32_t r0, r1, r2, r3;
                ldsm4(r0, r1, r2, r3, bB + boff0 + nb * 16 * AST * 2);
                bq[nb * 2 + 0][0] = r0; bq[nb * 2 + 0][1] = r2;
                bq[nb * 2 + 1][0] = r1; bq[nb * 2 + 1][1] = r3;
            }
            #pragma unroll
            for (int mi = 0; mi < 4; mi++)
                #pragma unroll
                for (int ni = 0; ni < 4; ni++)
                    mma_f16(acc[mi][ni], a[mi], bq[ni]);
        }
        __syncthreads();
    }

    #pragma unroll
    for (int mi = 0; mi < 4; mi++) {
        #pragma unroll
        for (int ni = 0; ni < 4; ni++) {
            int r = m0 + wm + mi * 16 + (lane >> 2);
            int c = n0 + wn + ni * 8 + (lane & 3) * 2;
            float b0 = 0.f, b1 = 0.f;
            if (bias) { b0 = bias[c]; b1 = bias[c + 1]; }
            #pragma unroll
            for (int half = 0; half < 2; half++) {
                int rr = r + half * 8;
                float v0 = acc[mi][ni][half * 2 + 0] + b0;
                float v1 = acc[mi][ni][half * 2 + 1] + b1;
                if (res) {
                    float2 rv = *(const float2*)(res + (size_t)rr * N + c);
                    v0 += rv.x; v1 += rv.y;
                }
                if (relu) { v0 = fmaxf(v0, 0.f); v1 = fmaxf(v1, 0.f); }
                if (Cf)
                    *(float2*)(Cf + (size_t)rr * N + c) = make_float2(v0, v1);
                if (Oh)
                    *(uint32_t*)(Oh + (size_t)rr * N + c) = pack_f16x2(v0, v1);
            }
        }
    }
}

// ---------------------------------------------------------------------------
// Fused flash attention (fp16 HMMA, online softmax). Writes fp16.
// 128 Q rows per CTA, 256 threads (8 warps x 16 rows); K/V tiles of 64 rows
// are staged once per 128 Q rows (halved global K/V traffic vs 64-row tiles).
// Q, K, V read DIRECTLY from head-interleaved GEMM outputs:
//   row (b, s) at base[(b*448+s)*stride + off + h*64].
// V staged [s][d], consumed via ldmatrix.trans. Ragged last Q tile guarded.
// ---------------------------------------------------------------------------
__global__ __launch_bounds__(256) void flash_kernel(
    const __half* __restrict__ Qb, int qStride, int qOff,
    const __half* __restrict__ Kb, int kStride, int kOff,
    const __half* __restrict__ Vb, int vStride, int vOff,
    __half* __restrict__ Oh, int Tq, int Tk, float qscale, int causal)
{
    constexpr int ST = 72;
    __shared__ __half sQ[128 * ST];
    __shared__ __half sK[64 * ST];
    __shared__ __half sV[64 * ST];
    uint32_t bQ = smem_u32(sQ), bK = smem_u32(sK), bV = smem_u32(sV);

    int tid = threadIdx.x, lane = tid & 31, w = tid >> 5;   // 8 warps
    int qt = blockIdx.x, bh = blockIdx.y;
    int b = bh >> 4, h = bh & 15;
    int q0 = qt * 128;

    // stage Q tile (128 rows; zero-fill rows beyond Tq)
    const __half* Qp = Qb + (size_t)(b * 448 + q0) * qStride + qOff + h * 64;
    #pragma unroll
    for (int it = 0; it < 4; it++) {
        int idx = tid + it * 256;
        int row = idx >> 3, c8 = (idx & 7) * 8;
        uint4 v = make_uint4(0u, 0u, 0u, 0u);
        if (q0 + row < Tq)
            v = *(const uint4*)(Qp + (size_t)row * qStride + c8);
        *(uint4*)&sQ[row * ST + c8] = v;
    }
    __syncthreads();

    uint32_t qf[4][4];
    {
        int r = w * 16 + (lane & 15);
        #pragma unroll
        for (int ks = 0; ks < 4; ks++) {
            uint32_t addr = bQ + (uint32_t)(r * ST + ks * 16 + (lane >> 4) * 8) * 2;
            ldsm4(qf[ks][0], qf[ks][1], qf[ks][2], qf[ks][3], addr);
        }
    }

    float m[2] = {-1e30f, -1e30f}, l[2] = {0.f, 0.f};
    float o[8][4];
    #pragma unroll
    for (int i = 0; i < 8; i++)
        #pragma unroll
        for (int j = 0; j < 4; j++) o[i][j] = 0.f;

    int r0g = q0 + w * 16 + (lane >> 2);

    int nktAll = Tk >> 6;
    int nkt = causal ? min(nktAll, (qt + 1) * 2) : nktAll;
    for (int kt = 0; kt < nkt; kt++) {
        const __half* Kp = Kb + (size_t)(b * 448 + kt * 64) * kStride + kOff + h * 64;
        const __half* Vp = Vb + (size_t)(b * 448 + kt * 64) * vStride + vOff + h * 64;
        #pragma unroll
        for (int it = 0; it < 2; it++) {
            int idx = tid + it * 256;
            int row = idx >> 3, c8 = (idx & 7) * 8;
            *(uint4*)&sK[row * ST + c8] = *(const uint4*)(Kp + (size_t)row * kStride + c8);
            *(uint4*)&sV[row * ST + c8] = *(const uint4*)(Vp + (size_t)row * vStride + c8);
        }
        __syncthreads();

        float s_acc[8][4];
        #pragma unroll
        for (int i = 0; i < 8; i++)
            #pragma unroll
            for (int j = 0; j < 4; j++) s_acc[i][j] = 0.f;

        #pragma unroll
        for (int ng = 0; ng < 4; ng++) {
            int nrow = ng * 16 + (lane & 15);
            #pragma unroll
            for (int ks = 0; ks < 4; ks++) {
                uint32_t r0, r1, r2, r3;
                ldsm4(r0, r1, r2, r3,
                      bK + (uint32_t)(nrow * ST + ks * 16 + (lane >> 4) * 8) * 2);
                uint32_t b0[2] = {r0, r2}, b1[2] = {r1, r3};
                mma_f16(s_acc[ng * 2 + 0], qf[ks], b0);
                mma_f16(s_acc[ng * 2 + 1], qf[ks], b1);
            }
        }

        // softmax scale (uniform positive; applied before max/exp)
        #pragma unroll
        for (int i = 0; i < 8; i++)
            #pragma unroll
            for (int j = 0; j < 4; j++) s_acc[i][j] *= qscale;

        // diagonal-straddling tiles only
        if (causal && kt * 64 + 63 > q0) {
            #pragma unroll
            for (int nb = 0; nb < 8; nb++) {
                int cg = kt * 64 + nb * 8 + (lane & 3) * 2;
                #pragma unroll
                for (int half = 0; half < 2; half++) {
                    int rg = r0g + half * 8;
                    if (cg > rg)     s_acc[nb][half * 2 + 0] = -1e30f;
                    if (cg + 1 > rg) s_acc[nb][half * 2 + 1] = -1e30f;
                }
            }
        }

        float tmax[2] = {-1e30f, -1e30f};
        #pragma unroll
        for (int nb = 0; nb < 8; nb++) {
            tmax[0] = fmaxf(tmax[0], fmaxf(s_acc[nb][0], s_acc[nb][1]));
            tmax[1] = fmaxf(tmax[1], fmaxf(s_acc[nb][2], s_acc[nb][3]));
        }
        #pragma unroll
        for (int i = 0; i < 2; i++) {
            tmax[i] = fmaxf(tmax[i], __shfl_xor_sync(0xffffffffu, tmax[i], 1));
            tmax[i] = fmaxf(tmax[i], __shfl_xor_sync(0xffffffffu, tmax[i], 2));
        }
        float mn[2] = {fmaxf(m[0], tmax[0]), fmaxf(m[1], tmax[1])};
        float fac[2] = {__expf(m[0] - mn[0]), __expf(m[1] - mn[1])};
        m[0] = mn[0]; m[1] = mn[1];

        uint32_t pf[4][4];
        float rs[2] = {0.f, 0.f};
        #pragma unroll
        for (int nb = 0; nb < 8; nb++) {
            float e0 = __expf(s_acc[nb][0] - mn[0]);
            float e1 = __expf(s_acc[nb][1] - mn[0]);
            float e2 = __expf(s_acc[nb][2] - mn[1]);
            float e3 = __expf(s_acc[nb][3] - mn[1]);
            rs[0] += e0 + e1;
            rs[1] += e2 + e3;
            pf[nb >> 1][(nb & 1) * 2 + 0] = pack_f16x2(e0, e1);
            pf[nb >> 1][(nb & 1) * 2 + 1] = pack_f16x2(e2, e3);
        }
        #pragma unroll
        for (int i = 0; i < 2; i++) {
            rs[i] += __shfl_xor_sync(0xffffffffu, rs[i], 1);
            rs[i] += __shfl_xor_sync(0xffffffffu, rs[i], 2);
        }
        l[0] = l[0] * fac[0] + rs[0];
        l[1] = l[1] * fac[1] + rs[1];
        #pragma unroll
        for (int nb = 0; nb < 8; nb++) {
            o[nb][0] *= fac[0]; o[nb][1] *= fac[0];
            o[nb][2] *= fac[1]; o[nb][3] *= fac[1];
        }

        // O += P @ V : V staged [s][d], loaded via ldmatrix.trans.
        #pragma unroll
        for (int ng = 0; ng < 4; ng++) {
            #pragma unroll
            for (int ks = 0; ks < 4; ks++) {
                uint32_t t0, t1, t2, t3;
                ldsm4_t(t0, t1, t2, t3,
                        bV + (uint32_t)((ks * 16 + (lane & 15)) * ST
                                        + ng * 16 + (lane >> 4) * 8) * 2);
                uint32_t b0[2] = {t0, t1}, b1[2] = {t2, t3};
                mma_f16(o[ng * 2 + 0], pf[ks], b0);
                mma_f16(o[ng * 2 + 1], pf[ks], b1);
            }
        }
        __syncthreads();
    }

    float inv0 = 1.f / l[0], inv1 = 1.f / l[1];
    #pragma unroll
    for (int nb = 0; nb < 8; nb++) {
        int col = h * 64 + nb * 8 + (lane & 3) * 2;
        #pragma unroll
        for (int half = 0; half < 2; half++) {
            int rg = r0g + half * 8;
            if (rg < Tq) {
                float inv = half ? inv1 : inv0;
                float v0 = o[nb][half * 2 + 0] * inv;
                float v1 = o[nb][half * 2 + 1] * inv;
                size_t off = ((size_t)b * Tq + rg) * C + col;
                *(uint32_t*)(Oh + off) = pack_f16x2(v0, v1);
            }
        }
    }
}

// ---------------------------------------------------------------------------
// LayerNorm: one block per row, writes fp16
// ---------------------------------------------------------------------------
__inline__ __device__ float warp_sum(float v) {
    #pragma unroll
    for (int o = 16; o > 0; o >>= 1) v += __shfl_xor_sync(0xffffffffu, v, o);
    return v;
}

__global__ __launch_bounds__(256) void ln_kernel(
    const float* __restrict__ x, const float* __restrict__ g,
    const float* __restrict__ b, __half* __restrict__ oh)
{
    __shared__ float s_sum[8], s_sq[8];
    int tid = threadIdx.x;
    const float* xr = x + (size_t)blockIdx.x * C;
    float s = 0.f, s2 = 0.f;
    for (int i = tid; i < C; i += 256) { float v = xr[i]; s += v; s2 += v * v; }
    s = warp_sum(s); s2 = warp_sum(s2);
    if ((tid & 31) == 0) { s_sum[tid >> 5] = s; s_sq[tid >> 5] = s2; }
    __syncthreads();
    if (tid < 32) {
        float a  = tid < 8 ? s_sum[tid] : 0.f;
        float c2 = tid < 8 ? s_sq[tid]  : 0.f;
        a = warp_sum(a); c2 = warp_sum(c2);
        if (tid == 0) { s_sum[0] = a; s_sq[0] = c2; }
    }
    __syncthreads();
    float mean = s_sum[0] * (1.f / C);
    float var  = s_sq[0] * (1.f / C) - mean * mean;
    float rstd = rsqrtf(var + 1e-5f);
    size_t base = (size_t)blockIdx.x * C;
    for (int i = tid; i < C; i += 256) {
        float v = (xr[i] - mean) * rstd * g[i] + b[i];
        oh[base + i] = __float2half_rn(v);
    }
}

// ---------------------------------------------------------------------------
// Launch: full decoder block, 3-stream DAG
// ---------------------------------------------------------------------------
extern "C" void kernel_launch(void* const* d_in, const int* in_sizes, int n_in,
                              void* d_out, int out_size)
{
    (void)in_sizes; (void)n_in; (void)out_size;
    const float* tgt      = (const float*)d_in[0];
    const float* src      = (const float*)d_in[1];
    const float* sa_wqkv  = (const float*)d_in[2];
    const float* sa_wproj = (const float*)d_in[3];
    const float* sa_bproj = (const float*)d_in[4];
    const float* ed_wkv   = (const float*)d_in[5];
    const float* ed_wq    = (const float*)d_in[6];
    const float* ed_wproj = (const float*)d_in[7];
    const float* ed_bproj = (const float*)d_in[8];
    const float* ff_w1    = (const float*)d_in[9];
    const float* ff_b1    = (const float*)d_in[10];
    const float* ff_w2    = (const float*)d_in[11];
    const float* ff_b2    = (const float*)d_in[12];
    const float* ln1_g    = (const float*)d_in[13];
    const float* ln1_b    = (const float*)d_in[14];
    const float* ln2_g    = (const float*)d_in[15];
    const float* ln2_b    = (const float*)d_in[16];
    const float* ln3_g    = (const float*)d_in[17];
    const float* ln3_b    = (const float*)d_in[18];
    float* out = (float*)d_out;

    static __half *ln1p = nullptr, *ln2p, *ln3p, *op, *hid, *wt;
    static __half *x1, *x2, *x3;
    static cudaStream_t sA = nullptr, sB = nullptr;
    static cudaEvent_t e0 = nullptr, eKV = nullptr, eF1 = nullptr;
    if (!ln1p) {
        cudaGetSymbolAddress((void**)&ln1p, g_ln1);
        cudaGetSymbolAddress((void**)&ln2p, g_ln2);
        cudaGetSymbolAddress((void**)&ln3p, g_ln3);
        cudaGetSymbolAddress((void**)&op,   g_o);
        cudaGetSymbolAddress((void**)&hid,  g_hid);
        cudaGetSymbolAddress((void**)&wt,   g_wt);
        cudaGetSymbolAddress((void**)&x1,   g_x1);
        cudaGetSymbolAddress((void**)&x2,   g_x2);
        cudaGetSymbolAddress((void**)&x3,   g_x3);
        cudaStreamCreateWithFlags(&sA, cudaStreamNonBlocking);
        cudaStreamCreateWithFlags(&sB, cudaStreamNonBlocking);
        cudaEventCreateWithFlags(&e0,  cudaEventDisableTiming);
        cudaEventCreateWithFlags(&eKV, cudaEventDisableTiming);
        cudaEventCreateWithFlags(&eF1, cudaEventDisableTiming);
    }

    const float scale = 0.03125f;   // C^-0.5

    const size_t o_qkv = 0, o_sap = 3 * C2, o_kv = 4 * C2, o_q = 6 * C2,
                 o_edp = 7 * C2, o_f1 = 8 * C2, o_f2 = 12 * C2;

    const int QTILES = (T + 127) / 128;   // 4 (last tile ragged)

    // ---- fork ----
    cudaEventRecord(e0, 0);
    cudaStreamWaitEvent(sA, e0, 0);
    cudaStreamWaitEvent(sB, e0, 0);

    // ---- branch A (stream sA): cross-attention K/V from src ----
    wconv_kernel<<<dim3(2 * C / 32, C / 32), 256, 0, sA>>>(ed_wkv, wt + o_kv, C, 2 * C);
    ln_kernel<<<B * J, 256, 0, sA>>>(src, ln2_g, ln2_b, ln2p);
    hmma_gemm<<<dim3(2 * C / 128, (B * J) / 128), 256, 0, sA>>>(
        ln2p, wt + o_kv, nullptr, nullptr, nullptr, x2, B * J, 2 * C, C, 0);
    cudaEventRecord(eKV, sA);

    // ---- branch B (stream sB): FFN hidden from tgt ----
    wconv_kernel<<<dim3(4 * C / 32, C / 32), 256, 0, sB>>>(ff_w1, wt + o_f1, C, 4 * C);
    wconv_kernel<<<dim3(C / 32, 4 * C / 32), 256, 0, sB>>>(ff_w2, wt + o_f2, 4 * C, C);
    ln_kernel<<<ROWS, 256, 0, sB>>>(tgt, ln3_g, ln3_b, ln3p);
    hmma_gemm<<<dim3(4 * C / 128, ROWS / 128), 256, 0, sB>>>(
        ln3p, wt + o_f1, ff_b1, nullptr, nullptr, hid, ROWS, 4 * C, C, 1);
    cudaEventRecord(eF1, sB);

    // ---- origin stream: critical path ----
    wconv_kernel<<<dim3(3 * C / 32, C / 32), 256>>>(sa_wqkv,  wt + o_qkv, C, 3 * C);
    wconv_kernel<<<dim3(C / 32, C / 32),     256>>>(sa_wproj, wt + o_sap, C, C);
    wconv_kernel<<<dim3(C / 32, C / 32),     256>>>(ed_wq,    wt + o_q,   C, C);
    wconv_kernel<<<dim3(C / 32, C / 32),     256>>>(ed_wproj, wt + o_edp, C, C);
    ln_kernel<<<ROWS, 256>>>(tgt, ln1_g, ln1_b, ln1p);
    hmma_gemm<<<dim3(3 * C / 128, ROWS / 128), 256>>>(
        ln1p, wt + o_qkv, nullptr, nullptr, nullptr, x1, ROWS, 3 * C, C, 0);
    flash_kernel<<<dim3(QTILES, B * H), 256>>>(
        x1, 3 * C, 0, x1, 3 * C, C, x1, 3 * C, 2 * C, op, T, T, scale, 1);
    hmma_gemm<<<dim3(C / 128, ROWS / 128), 256>>>(
        op, wt + o_sap, sa_bproj, tgt, out, nullptr, ROWS, C, C, 0);
    ln_kernel<<<ROWS, 256>>>(out, ln2_g, ln2_b, ln1p);
    hmma_gemm<<<dim3(C / 128, ROWS / 128), 256>>>(
        ln1p, wt + o_q, nullptr, nullptr, nullptr, x3, ROWS, C, C, 0);

    cudaStreamWaitEvent(0, eKV, 0);      // join branch A
    flash_kernel<<<dim3(QTILES, B * H), 256>>>(
        x3, C, 0, x2, 2 * C, 0, x2, 2 * C, C, op, T, J, scale, 0);
    hmma_gemm<<<dim3(C / 128, ROWS / 128), 256>>>(
        op, wt + o_edp, ed_bproj, out, out, nullptr, ROWS, C, C, 0);

    cudaStreamWaitEvent(0, eF1, 0);      // join branch B
    hmma_gemm<<<dim3(C / 128, ROWS / 128), 256>>>(
        hid, wt + o_f2, ff_b2, out, out, nullptr, ROWS, C, 4 * C, 0);
}

// round 16
// speedup vs baseline: 1.0317x; 1.0317x over previous
#include <cuda_runtime.h>
#include <cuda_fp16.h>
#include <cstdint>
#include <cstddef>

// Problem constants
constexpr int B  = 16;
constexpr int T  = 448;
constexpr int J  = 448;
constexpr int C  = 1024;
constexpr int H  = 16;
constexpr int HD = 64;
constexpr int ROWS = B * T;          // 7168 (== B*J)
constexpr size_t C2 = (size_t)C * C;

// ---------------------------------------------------------------------------
// Scratch (static device globals; no allocation allowed)
// ---------------------------------------------------------------------------
__device__ __half g_ln1[(size_t)ROWS * C];                // ln1 / ln2(out) (origin)
__device__ __half g_ln2[(size_t)ROWS * C];                // ln2(src) (branch A)
__device__ __half g_ln3[(size_t)ROWS * C];                // ln3 (branch B)
__device__ __half g_o  [(size_t)ROWS * C];                // flash out (origin)
__device__ __half g_hid[(size_t)ROWS * 4 * C];            // ffn hidden (branch B)
__device__ __half g_wt [16 * C2];                         // weights fp16 [N,K]
__device__ __half g_x1 [(size_t)ROWS * 3 * C];            // qkv fp16 out (origin)
__device__ __half g_x2 [(size_t)ROWS * 2 * C];            // kv fp16 out (branch A)
__device__ __half g_x3 [(size_t)ROWS * C];                // q2 fp16 out (origin)

// ---------------------------------------------------------------------------
// PTX helpers (family-agnostic: legal at compute_103)
// ---------------------------------------------------------------------------
__device__ __forceinline__ uint32_t smem_u32(const void* p) {
    uint32_t a;
    asm("{ .reg .u64 t; cvta.to.shared.u64 t, %1; cvt.u32.u64 %0, t; }"
        : "=r"(a) : "l"(p));
    return a;
}

__device__ __forceinline__ void ldsm4(uint32_t& r0, uint32_t& r1,
                                      uint32_t& r2, uint32_t& r3, uint32_t addr) {
    asm volatile("ldmatrix.sync.aligned.m8n8.x4.shared.b16 {%0,%1,%2,%3}, [%4];"
        : "=r"(r0), "=r"(r1), "=r"(r2), "=r"(r3) : "r"(addr));
}

__device__ __forceinline__ void ldsm4_t(uint32_t& r0, uint32_t& r1,
                                        uint32_t& r2, uint32_t& r3, uint32_t addr) {
    asm volatile("ldmatrix.sync.aligned.m8n8.x4.trans.shared.b16 {%0,%1,%2,%3}, [%4];"
        : "=r"(r0), "=r"(r1), "=r"(r2), "=r"(r3) : "r"(addr));
}

__device__ __forceinline__ void mma_f16(float* c, const uint32_t* a, const uint32_t* b) {
    asm volatile("mma.sync.aligned.m16n8k16.row.col.f32.f16.f16.f32 "
        "{%0,%1,%2,%3}, {%4,%5,%6,%7}, {%8,%9}, {%0,%1,%2,%3};"
        : "+f"(c[0]), "+f"(c[1]), "+f"(c[2]), "+f"(c[3])
        : "r"(a[0]), "r"(a[1]), "r"(a[2]), "r"(a[3]), "r"(b[0]), "r"(b[1]));
}

__device__ __forceinline__ uint32_t pack_f16x2(float a, float b) {
    uint32_t r;
    asm("cvt.rn.f16x2.f32 %0, %1, %2;" : "=r"(r) : "f"(b), "f"(a));
    return r;
}

__device__ __forceinline__ void cp16(uint32_t dst, const void* src) {
    asm volatile("cp.async.cg.shared.global [%0], [%1], 16;" :: "r"(dst), "l"(src));
}
__device__ __forceinline__ void cp_commit() {
    asm volatile("cp.async.commit_group;" ::: "memory");
}

// ---------------------------------------------------------------------------
// Weight transpose + fp32 -> fp16:  W[K,N] -> Wt[N,K]
// ---------------------------------------------------------------------------
__global__ __launch_bounds__(256) void wconv_kernel(
    const float* __restrict__ W, __half* __restrict__ Wt, int K, int N)
{
    __shared__ float t[32][33];
    int tx = threadIdx.x & 31, ty = threadIdx.x >> 5;
    int n0 = blockIdx.x * 32, k0 = blockIdx.y * 32;
    #pragma unroll
    for (int i = 0; i < 4; i++)
        t[ty + i * 8][tx] = W[(size_t)(k0 + ty + i * 8) * N + n0 + tx];
    __syncthreads();
    #pragma unroll
    for (int i = 0; i < 4; i++) {
        int n = ty + i * 8;
        Wt[(size_t)(n0 + n) * K + k0 + tx] = __float2half_rn(t[tx][n]);
    }
}

// ---------------------------------------------------------------------------
// HMMA GEMM, single-pass fp16, 2-stage cp.async pipeline (proven).
// A fp16 [M,K]; B fp16 [N,K]. Tile 128x128, BK=32, 256 threads.
// Output: fp32 Cf (+bias/res/relu) and/or fp16 Oh [M,N] (both coalesced).
// ---------------------------------------------------------------------------
constexpr int AST  = 40;                 // smem row stride (fp16 elems), 80B
constexpr int TBUF = 128 * AST;          // elems per tile

__global__ __launch_bounds__(256) void hmma_gemm(
    const __half* __restrict__ Ap, const __half* __restrict__ Bp,
    const float* __restrict__ bias, const float* __restrict__ res,
    float* __restrict__ Cf, __half* __restrict__ Oh,
    int M, int N, int K, int relu)
{
    __shared__ __half smbuf[2 * 2 * TBUF];   // 2 stages x {A,B} = 40 KB
    uint32_t sbase = smem_u32(smbuf);

    int tid = threadIdx.x, lane = tid & 31, w = tid >> 5;
    int wm = (w & 1) * 64, wn = (w >> 1) * 32;
    int m0 = blockIdx.y * 128, n0 = blockIdx.x * 128;

    float acc[4][4][4];
    #pragma unroll
    for (int i = 0; i < 4; i++)
        #pragma unroll
        for (int j = 0; j < 4; j++)
            #pragma unroll
            for (int r = 0; r < 4; r++) acc[i][j][r] = 0.f;

    const int nch = K >> 5;
    const int row = tid >> 2, seg = tid & 3;

    auto stage = [&](int kc, int s) {
        uint32_t base = sbase + (uint32_t)s * 2 * TBUF * 2;
        const size_t ka = (size_t)kc * 32;
        #pragma unroll
        for (int it = 0; it < 2; it++) {
            int r = row + it * 64;
            uint32_t so = (uint32_t)r * 80 + seg * 16;
            cp16(base + so,            Ap + (size_t)(m0 + r) * K + ka + seg * 8);
            cp16(base + TBUF * 2 + so, Bp + (size_t)(n0 + r) * K + ka + seg * 8);
        }
    };

    stage(0, 0);
    cp_commit();

    for (int kc = 0; kc < nch; kc++) {
        if (kc + 1 < nch) {
            stage(kc + 1, (kc + 1) & 1);
            cp_commit();
            asm volatile("cp.async.wait_group 1;" ::: "memory");
        } else {
            asm volatile("cp.async.wait_group 0;" ::: "memory");
        }
        __syncthreads();

        uint32_t base = sbase + (uint32_t)(kc & 1) * 2 * TBUF * 2;
        uint32_t bA = base, bB = base + TBUF * 2;

        #pragma unroll
        for (int ks = 0; ks < 2; ks++) {
            int arow = wm + (lane & 15);
            int akk  = ks * 16 + (lane >> 4) * 8;
            uint32_t aoff = (uint32_t)(arow * AST + akk) * 2;

            uint32_t a[4][4], bq[4][2];
            #pragma unroll
            for (int mi = 0; mi < 4; mi++)
                ldsm4(a[mi][0], a[mi][1], a[mi][2], a[mi][3],
                      bA + aoff + mi * 16 * AST * 2);
            int brow = wn + (lane & 15);
            uint32_t boff0 = (uint32_t)(brow * AST + akk) * 2;
            #pragma unroll
            for (int nb = 0; nb < 2; nb++) {
                uint32_t r0, r1, r2, r3;
                ldsm4(r0, r1, r2, r3, bB + boff0 + nb * 16 * AST * 2);
                bq[nb * 2 + 0][0] = r0; bq[nb * 2 + 0][1] = r2;
                bq[nb * 2 + 1][0] = r1; bq[nb * 2 + 1][1] = r3;
            }
            #pragma unroll
            for (int mi = 0; mi < 4; mi++)
                #pragma unroll
                for (int ni = 0; ni < 4; ni++)
                    mma_f16(acc[mi][ni], a[mi], bq[ni]);
        }
        __syncthreads();
    }

    #pragma unroll
    for (int mi = 0; mi < 4; mi++) {
        #pragma unroll
        for (int ni = 0; ni < 4; ni++) {
            int r = m0 + wm + mi * 16 + (lane >> 2);
            int c = n0 + wn + ni * 8 + (lane & 3) * 2;
            float b0 = 0.f, b1 = 0.f;
            if (bias) { b0 = bias[c]; b1 = bias[c + 1]; }
            #pragma unroll
            for (int half = 0; half < 2; half++) {
                int rr = r + half * 8;
                float v0 = acc[mi][ni][half * 2 + 0] + b0;
                float v1 = acc[mi][ni][half * 2 + 1] + b1;
                if (res) {
                    float2 rv = *(const float2*)(res + (size_t)rr * N + c);
                    v0 += rv.x; v1 += rv.y;
                }
                if (relu) { v0 = fmaxf(v0, 0.f); v1 = fmaxf(v1, 0.f); }
                if (Cf)
                    *(float2*)(Cf + (size_t)rr * N + c) = make_float2(v0, v1);
                if (Oh)
                    *(uint32_t*)(Oh + (size_t)rr * N + c) = pack_f16x2(v0, v1);
            }
        }
    }
}

// ---------------------------------------------------------------------------
// Fused flash attention (fp16 HMMA, online softmax). Writes fp16.
// Round-13 tiling (64 Q rows, 128 threads, 4 warps) + cp.async
// double-buffered K/V staging (GEMM-proven pattern).
// Q, K, V read DIRECTLY from head-interleaved GEMM outputs:
//   row (b, s) at base[(b*448+s)*stride + off + h*64].
// V staged [s][d], consumed via ldmatrix.trans.
// ---------------------------------------------------------------------------
__global__ __launch_bounds__(128) void flash_kernel(
    const __half* __restrict__ Qb, int qStride, int qOff,
    const __half* __restrict__ Kb, int kStride, int kOff,
    const __half* __restrict__ Vb, int vStride, int vOff,
    __half* __restrict__ Oh, int Tq, int Tk, float qscale, int causal)
{
    constexpr int ST = 72;               // halves; row = 144 B = 9 x 16 B
    constexpr int KVB = 64 * ST;         // halves per K/V buffer
    __shared__ __half sQ[64 * ST];
    __shared__ __half sK[2 * KVB];
    __shared__ __half sV[2 * KVB];
    uint32_t bQ = smem_u32(sQ), bK0 = smem_u32(sK), bV0 = smem_u32(sV);

    int tid = threadIdx.x, lane = tid & 31, w = tid >> 5;
    int qt = blockIdx.x, bh = blockIdx.y;
    int b = bh >> 4, h = bh & 15;
    int q0 = qt * 64;

    // stage K/V tile kt into buffer s via cp.async
    auto stageKV = [&](int kt, int s) {
        const __half* Kp = Kb + (size_t)(b * 448 + kt * 64) * kStride + kOff + h * 64;
        const __half* Vp = Vb + (size_t)(b * 448 + kt * 64) * vStride + vOff + h * 64;
        uint32_t kb = bK0 + (uint32_t)s * KVB * 2;
        uint32_t vb = bV0 + (uint32_t)s * KVB * 2;
        #pragma unroll
        for (int it = 0; it < 4; it++) {
            int idx = tid + it * 128;
            int row = idx >> 3, c8 = (idx & 7) * 8;
            uint32_t so = (uint32_t)(row * ST + c8) * 2;
            cp16(kb + so, Kp + (size_t)row * kStride + c8);
            cp16(vb + so, Vp + (size_t)row * vStride + c8);
        }
    };

    // stage Q tile (plain stores)
    const __half* Qp = Qb + (size_t)(b * 448 + q0) * qStride + qOff + h * 64;
    #pragma unroll
    for (int it = 0; it < 4; it++) {
        int idx = tid + it * 128;
        int row = idx >> 3, c8 = (idx & 7) * 8;
        *(uint4*)&sQ[row * ST + c8] = *(const uint4*)(Qp + (size_t)row * qStride + c8);
    }

    stageKV(0, 0);
    cp_commit();
    __syncthreads();

    uint32_t qf[4][4];
    {
        int r = w * 16 + (lane & 15);
        #pragma unroll
        for (int ks = 0; ks < 4; ks++) {
            uint32_t addr = bQ + (uint32_t)(r * ST + ks * 16 + (lane >> 4) * 8) * 2;
            ldsm4(qf[ks][0], qf[ks][1], qf[ks][2], qf[ks][3], addr);
        }
    }

    float m[2] = {-1e30f, -1e30f}, l[2] = {0.f, 0.f};
    float o[8][4];
    #pragma unroll
    for (int i = 0; i < 8; i++)
        #pragma unroll
        for (int j = 0; j < 4; j++) o[i][j] = 0.f;

    int r0g = q0 + w * 16 + (lane >> 2);

    int nkt = causal ? (qt + 1) : (Tk >> 6);
    for (int kt = 0; kt < nkt; kt++) {
        if (kt + 1 < nkt) {
            stageKV(kt + 1, (kt + 1) & 1);
            cp_commit();
            asm volatile("cp.async.wait_group 1;" ::: "memory");
        } else {
            asm volatile("cp.async.wait_group 0;" ::: "memory");
        }
        __syncthreads();

        uint32_t bK = bK0 + (uint32_t)(kt & 1) * KVB * 2;
        uint32_t bV = bV0 + (uint32_t)(kt & 1) * KVB * 2;

        float s_acc[8][4];
        #pragma unroll
        for (int i = 0; i < 8; i++)
            #pragma unroll
            for (int j = 0; j < 4; j++) s_acc[i][j] = 0.f;

        #pragma unroll
        for (int ng = 0; ng < 4; ng++) {
            int nrow = ng * 16 + (lane & 15);
            #pragma unroll
            for (int ks = 0; ks < 4; ks++) {
                uint32_t r0, r1, r2, r3;
                ldsm4(r0, r1, r2, r3,
                      bK + (uint32_t)(nrow * ST + ks * 16 + (lane >> 4) * 8) * 2);
                uint32_t b0[2] = {r0, r2}, b1[2] = {r1, r3};
                mma_f16(s_acc[ng * 2 + 0], qf[ks], b0);
                mma_f16(s_acc[ng * 2 + 1], qf[ks], b1);
            }
        }

        // softmax scale (uniform positive; applied before max/exp)
        #pragma unroll
        for (int i = 0; i < 8; i++)
            #pragma unroll
            for (int j = 0; j < 4; j++) s_acc[i][j] *= qscale;

        if (causal && kt == qt) {
            #pragma unroll
            for (int nb = 0; nb < 8; nb++) {
                int cg = kt * 64 + nb * 8 + (lane & 3) * 2;
                #pragma unroll
                for (int half = 0; half < 2; half++) {
                    int rg = r0g + half * 8;
                    if (cg > rg)     s_acc[nb][half * 2 + 0] = -1e30f;
                    if (cg + 1 > rg) s_acc[nb][half * 2 + 1] = -1e30f;
                }
            }
        }

        float tmax[2] = {-1e30f, -1e30f};
        #pragma unroll
        for (int nb = 0; nb < 8; nb++) {
            tmax[0] = fmaxf(tmax[0], fmaxf(s_acc[nb][0], s_acc[nb][1]));
            tmax[1] = fmaxf(tmax[1], fmaxf(s_acc[nb][2], s_acc[nb][3]));
        }
        #pragma unroll
        for (int i = 0; i < 2; i++) {
            tmax[i] = fmaxf(tmax[i], __shfl_xor_sync(0xffffffffu, tmax[i], 1));
            tmax[i] = fmaxf(tmax[i], __shfl_xor_sync(0xffffffffu, tmax[i], 2));
        }
        float mn[2] = {fmaxf(m[0], tmax[0]), fmaxf(m[1], tmax[1])};
        float fac[2] = {__expf(m[0] - mn[0]), __expf(m[1] - mn[1])};
        m[0] = mn[0]; m[1] = mn[1];

        uint32_t pf[4][4];
        float rs[2] = {0.f, 0.f};
        #pragma unroll
        for (int nb = 0; nb < 8; nb++) {
            float e0 = __expf(s_acc[nb][0] - mn[0]);
            float e1 = __expf(s_acc[nb][1] - mn[0]);
            float e2 = __expf(s_acc[nb][2] - mn[1]);
            float e3 = __expf(s_acc[nb][3] - mn[1]);
            rs[0] += e0 + e1;
            rs[1] += e2 + e3;
            pf[nb >> 1][(nb & 1) * 2 + 0] = pack_f16x2(e0, e1);
            pf[nb >> 1][(nb & 1) * 2 + 1] = pack_f16x2(e2, e3);
        }
        #pragma unroll
        for (int i = 0; i < 2; i++) {
            rs[i] += __shfl_xor_sync(0xffffffffu, rs[i], 1);
            rs[i] += __shfl_xor_sync(0xffffffffu, rs[i], 2);
        }
        l[0] = l[0] * fac[0] + rs[0];
        l[1] = l[1] * fac[1] + rs[1];
        #pragma unroll
        for (int nb = 0; nb < 8; nb++) {
            o[nb][0] *= fac[0]; o[nb][1] *= fac[0];
            o[nb][2] *= fac[1]; o[nb][3] *= fac[1];
        }

        // O += P @ V : V staged [s][d], loaded via ldmatrix.trans.
        #pragma unroll
        for (int ng = 0; ng < 4; ng++) {
            #pragma unroll
            for (int ks = 0; ks < 4; ks++) {
                uint32_t t0, t1, t2, t3;
                ldsm4_t(t0, t1, t2, t3,
                        bV + (uint32_t)((ks * 16 + (lane & 15)) * ST
                                        + ng * 16 + (lane >> 4) * 8) * 2);
                uint32_t b0[2] = {t0, t1}, b1[2] = {t2, t3};
                mma_f16(o[ng * 2 + 0], pf[ks], b0);
                mma_f16(o[ng * 2 + 1], pf[ks], b1);
            }
        }
        __syncthreads();
    }

    float inv0 = 1.f / l[0], inv1 = 1.f / l[1];
    #pragma unroll
    for (int nb = 0; nb < 8; nb++) {
        int col = h * 64 + nb * 8 + (lane & 3) * 2;
        #pragma unroll
        for (int half = 0; half < 2; half++) {
            float inv = half ? inv1 : inv0;
            float v0 = o[nb][half * 2 + 0] * inv;
            float v1 = o[nb][half * 2 + 1] * inv;
            size_t off = ((size_t)b * Tq + r0g + half * 8) * C + col;
            *(uint32_t*)(Oh + off) = pack_f16x2(v0, v1);
        }
    }
}

// ---------------------------------------------------------------------------
// LayerNorm: one block per row, writes fp16
// ---------------------------------------------------------------------------
__inline__ __device__ float warp_sum(float v) {
    #pragma unroll
    for (int o = 16; o > 0; o >>= 1) v += __shfl_xor_sync(0xffffffffu, v, o);
    return v;
}

__global__ __launch_bounds__(256) void ln_kernel(
    const float* __restrict__ x, const float* __restrict__ g,
    const float* __restrict__ b, __half* __restrict__ oh)
{
    __shared__ float s_sum[8], s_sq[8];
    int tid = threadIdx.x;
    const float* xr = x + (size_t)blockIdx.x * C;
    float s = 0.f, s2 = 0.f;
    for (int i = tid; i < C; i += 256) { float v = xr[i]; s += v; s2 += v * v; }
    s = warp_sum(s); s2 = warp_sum(s2);
    if ((tid & 31) == 0) { s_sum[tid >> 5] = s; s_sq[tid >> 5] = s2; }
    __syncthreads();
    if (tid < 32) {
        float a  = tid < 8 ? s_sum[tid] : 0.f;
        float c2 = tid < 8 ? s_sq[tid]  : 0.f;
        a = warp_sum(a); c2 = warp_sum(c2);
        if (tid == 0) { s_sum[0] = a; s_sq[0] = c2; }
    }
    __syncthreads();
    float mean = s_sum[0] * (1.f / C);
    float var  = s_sq[0] * (1.f / C) - mean * mean;
    float rstd = rsqrtf(var + 1e-5f);
    size_t base = (size_t)blockIdx.x * C;
    for (int i = tid; i < C; i += 256) {
        float v = (xr[i] - mean) * rstd * g[i] + b[i];
        oh[base + i] = __float2half_rn(v);
    }
}

// ---------------------------------------------------------------------------
// Launch: full decoder block, 3-stream DAG
// ---------------------------------------------------------------------------
extern "C" void kernel_launch(void* const* d_in, const int* in_sizes, int n_in,
                              void* d_out, int out_size)
{
    (void)in_sizes; (void)n_in; (void)out_size;
    const float* tgt      = (const float*)d_in[0];
    const float* src      = (const float*)d_in[1];
    const float* sa_wqkv  = (const float*)d_in[2];
    const float* sa_wproj = (const float*)d_in[3];
    const float* sa_bproj = (const float*)d_in[4];
    const float* ed_wkv   = (const float*)d_in[5];
    const float* ed_wq    = (const float*)d_in[6];
    const float* ed_wproj = (const float*)d_in[7];
    const float* ed_bproj = (const float*)d_in[8];
    const float* ff_w1    = (const float*)d_in[9];
    const float* ff_b1    = (const float*)d_in[10];
    const float* ff_w2    = (const float*)d_in[11];
    const float* ff_b2    = (const float*)d_in[12];
    const float* ln1_g    = (const float*)d_in[13];
    const float* ln1_b    = (const float*)d_in[14];
    const float* ln2_g    = (const float*)d_in[15];
    const float* ln2_b    = (const float*)d_in[16];
    const float* ln3_g    = (const float*)d_in[17];
    const float* ln3_b    = (const float*)d_in[18];
    float* out = (float*)d_out;

    static __half *ln1p = nullptr, *ln2p, *ln3p, *op, *hid, *wt;
    static __half *x1, *x2, *x3;
    static cudaStream_t sA = nullptr, sB = nullptr;
    static cudaEvent_t e0 = nullptr, eKV = nullptr, eF1 = nullptr;
    if (!ln1p) {
        cudaGetSymbolAddress((void**)&ln1p, g_ln1);
        cudaGetSymbolAddress((void**)&ln2p, g_ln2);
        cudaGetSymbolAddress((void**)&ln3p, g_ln3);
        cudaGetSymbolAddress((void**)&op,   g_o);
        cudaGetSymbolAddress((void**)&hid,  g_hid);
        cudaGetSymbolAddress((void**)&wt,   g_wt);
        cudaGetSymbolAddress((void**)&x1,   g_x1);
        cudaGetSymbolAddress((void**)&x2,   g_x2);
        cudaGetSymbolAddress((void**)&x3,   g_x3);
        cudaStreamCreateWithFlags(&sA, cudaStreamNonBlocking);
        cudaStreamCreateWithFlags(&sB, cudaStreamNonBlocking);
        cudaEventCreateWithFlags(&e0,  cudaEventDisableTiming);
        cudaEventCreateWithFlags(&eKV, cudaEventDisableTiming);
        cudaEventCreateWithFlags(&eF1, cudaEventDisableTiming);
    }

    const float scale = 0.03125f;   // C^-0.5

    const size_t o_qkv = 0, o_sap = 3 * C2, o_kv = 4 * C2, o_q = 6 * C2,
                 o_edp = 7 * C2, o_f1 = 8 * C2, o_f2 = 12 * C2;

    // ---- fork ----
    cudaEventRecord(e0, 0);
    cudaStreamWaitEvent(sA, e0, 0);
    cudaStreamWaitEvent(sB, e0, 0);

    // ---- branch A (stream sA): cross-attention K/V from src ----
    wconv_kernel<<<dim3(2 * C / 32, C / 32), 256, 0, sA>>>(ed_wkv, wt + o_kv, C, 2 * C);
    ln_kernel<<<B * J, 256, 0, sA>>>(src, ln2_g, ln2_b, ln2p);
    hmma_gemm<<<dim3(2 * C / 128, (B * J) / 128), 256, 0, sA>>>(
        ln2p, wt + o_kv, nullptr, nullptr, nullptr, x2, B * J, 2 * C, C, 0);
    cudaEventRecord(eKV, sA);

    // ---- branch B (stream sB): FFN hidden from tgt ----
    wconv_kernel<<<dim3(4 * C / 32, C / 32), 256, 0, sB>>>(ff_w1, wt + o_f1, C, 4 * C);
    wconv_kernel<<<dim3(C / 32, 4 * C / 32), 256, 0, sB>>>(ff_w2, wt + o_f2, 4 * C, C);
    ln_kernel<<<ROWS, 256, 0, sB>>>(tgt, ln3_g, ln3_b, ln3p);
    hmma_gemm<<<dim3(4 * C / 128, ROWS / 128), 256, 0, sB>>>(
        ln3p, wt + o_f1, ff_b1, nullptr, nullptr, hid, ROWS, 4 * C, C, 1);
    cudaEventRecord(eF1, sB);

    // ---- origin stream: critical path ----
    wconv_kernel<<<dim3(3 * C / 32, C / 32), 256>>>(sa_wqkv,  wt + o_qkv, C, 3 * C);
    wconv_kernel<<<dim3(C / 32, C / 32),     256>>>(sa_wproj, wt + o_sap, C, C);
    wconv_kernel<<<dim3(C / 32, C / 32),     256>>>(ed_wq,    wt + o_q,   C, C);
    wconv_kernel<<<dim3(C / 32, C / 32),     256>>>(ed_wproj, wt + o_edp, C, C);
    ln_kernel<<<ROWS, 256>>>(tgt, ln1_g, ln1_b, ln1p);
    hmma_gemm<<<dim3(3 * C / 128, ROWS / 128), 256>>>(
        ln1p, wt + o_qkv, nullptr, nullptr, nullptr, x1, ROWS, 3 * C, C, 0);
    flash_kernel<<<dim3(T / 64, B * H), 128>>>(
        x1, 3 * C, 0, x1, 3 * C, C, x1, 3 * C, 2 * C, op, T, T, scale, 1);
    hmma_gemm<<<dim3(C / 128, ROWS / 128), 256>>>(
        op, wt + o_sap, sa_bproj, tgt, out, nullptr, ROWS, C, C, 0);
    ln_kernel<<<ROWS, 256>>>(out, ln2_g, ln2_b, ln1p);
    hmma_gemm<<<dim3(C / 128, ROWS / 128), 256>>>(
        ln1p, wt + o_q, nullptr, nullptr, nullptr, x3, ROWS, C, C, 0);

    cudaStreamWaitEvent(0, eKV, 0);      // join branch A
    flash_kernel<<<dim3(T / 64, B * H), 128>>>(
        x3, C, 0, x2, 2 * C, 0, x2, 2 * C, C, op, T, J, scale, 0);
    hmma_gemm<<<dim3(C / 128, ROWS / 128), 256>>>(
        op, wt + o_edp, ed_bproj, out, out, nullptr, ROWS, C, C, 0);

    cudaStreamWaitEvent(0, eF1, 0);      // join branch B
    hmma_gemm<<<dim3(C / 128, ROWS / 128), 256>>>(
        hid, wt + o_f2, ff_b2, out, out, nullptr, ROWS, C, 4 * C, 0);
}

// round 17
// speedup vs baseline: 1.0415x; 1.0095x over previous
#include <cuda_runtime.h>
#include <cuda_fp16.h>
#include <cstdint>
#include <cstddef>

// Problem constants
constexpr int B  = 16;
constexpr int T  = 448;
constexpr int J  = 448;
constexpr int C  = 1024;
constexpr int H  = 16;
constexpr int HD = 64;
constexpr int ROWS = B * T;          // 7168 (== B*J)
constexpr size_t C2 = (size_t)C * C;

// ---------------------------------------------------------------------------
// Scratch (static device globals; no allocation allowed)
// ---------------------------------------------------------------------------
__device__ __half g_ln1[(size_t)ROWS * C];                // ln1 / ln2(out) (origin)
__device__ __half g_ln2[(size_t)ROWS * C];                // ln2(src) (branch A)
__device__ __half g_ln3[(size_t)ROWS * C];                // ln3 (branch B)
__device__ __half g_o  [(size_t)ROWS * C];                // flash out (origin)
__device__ __half g_hid[(size_t)ROWS * 4 * C];            // ffn hidden (branch B)
__device__ __half g_wt [16 * C2];                         // weights fp16 [N,K]
__device__ __half g_x1 [(size_t)ROWS * 3 * C];            // qkv fp16 out (origin)
__device__ __half g_x2 [(size_t)ROWS * 2 * C];            // kv fp16 out (branch A)
__device__ __half g_x3 [(size_t)ROWS * C];                // q2 fp16 out (origin)

// ---------------------------------------------------------------------------
// PTX helpers (family-agnostic: legal at compute_103)
// ---------------------------------------------------------------------------
__device__ __forceinline__ uint32_t smem_u32(const void* p) {
    uint32_t a;
    asm("{ .reg .u64 t; cvta.to.shared.u64 t, %1; cvt.u32.u64 %0, t; }"
        : "=r"(a) : "l"(p));
    return a;
}

__device__ __forceinline__ void ldsm4(uint32_t& r0, uint32_t& r1,
                                      uint32_t& r2, uint32_t& r3, uint32_t addr) {
    asm volatile("ldmatrix.sync.aligned.m8n8.x4.shared.b16 {%0,%1,%2,%3}, [%4];"
        : "=r"(r0), "=r"(r1), "=r"(r2), "=r"(r3) : "r"(addr));
}

__device__ __forceinline__ void ldsm4_t(uint32_t& r0, uint32_t& r1,
                                        uint32_t& r2, uint32_t& r3, uint32_t addr) {
    asm volatile("ldmatrix.sync.aligned.m8n8.x4.trans.shared.b16 {%0,%1,%2,%3}, [%4];"
        : "=r"(r0), "=r"(r1), "=r"(r2), "=r"(r3) : "r"(addr));
}

__device__ __forceinline__ void mma_f16(float* c, const uint32_t* a, const uint32_t* b) {
    asm volatile("mma.sync.aligned.m16n8k16.row.col.f32.f16.f16.f32 "
        "{%0,%1,%2,%3}, {%4,%5,%6,%7}, {%8,%9}, {%0,%1,%2,%3};"
        : "+f"(c[0]), "+f"(c[1]), "+f"(c[2]), "+f"(c[3])
        : "r"(a[0]), "r"(a[1]), "r"(a[2]), "r"(a[3]), "r"(b[0]), "r"(b[1]));
}

__device__ __forceinline__ uint32_t pack_f16x2(float a, float b) {
    uint32_t r;
    asm("cvt.rn.f16x2.f32 %0, %1, %2;" : "=r"(r) : "f"(b), "f"(a));
    return r;
}

__device__ __forceinline__ void cp16(uint32_t dst, const void* src) {
    asm volatile("cp.async.cg.shared.global [%0], [%1], 16;" :: "r"(dst), "l"(src));
}
__device__ __forceinline__ void cp_commit() {
    asm volatile("cp.async.commit_group;" ::: "memory");
}

// ---------------------------------------------------------------------------
// Weight transpose + fp32 -> fp16:  W[K,N] -> Wt[N,K]
// ---------------------------------------------------------------------------
__global__ __launch_bounds__(256) void wconv_kernel(
    const float* __restrict__ W, __half* __restrict__ Wt, int K, int N)
{
    __shared__ float t[32][33];
    int tx = threadIdx.x & 31, ty = threadIdx.x >> 5;
    int n0 = blockIdx.x * 32, k0 = blockIdx.y * 32;
    #pragma unroll
    for (int i = 0; i < 4; i++)
        t[ty + i * 8][tx] = W[(size_t)(k0 + ty + i * 8) * N + n0 + tx];
    __syncthreads();
    #pragma unroll
    for (int i = 0; i < 4; i++) {
        int n = ty + i * 8;
        Wt[(size_t)(n0 + n) * K + k0 + tx] = __float2half_rn(t[tx][n]);
    }
}

// ---------------------------------------------------------------------------
// HMMA GEMM, single-pass fp16, 2-stage cp.async pipeline (proven).
// A fp16 [M,K]; B fp16 [N,K]. Tile 128x128, BK=32, 256 threads.
// Output: fp32 Cf (+bias/res/relu) and/or fp16 Oh [M,N] (both coalesced).
// ---------------------------------------------------------------------------
constexpr int AST  = 40;                 // smem row stride (fp16 elems), 80B
constexpr int TBUF = 128 * AST;          // elems per tile

__global__ __launch_bounds__(256) void hmma_gemm(
    const __half* __restrict__ Ap, const __half* __restrict__ Bp,
    const float* __restrict__ bias, const float* __restrict__ res,
    float* __restrict__ Cf, __half* __restrict__ Oh,
    int M, int N, int K, int relu)
{
    __shared__ __half smbuf[2 * 2 * TBUF];   // 2 stages x {A,B} = 40 KB
    uint32_t sbase = smem_u32(smbuf);

    int tid = threadIdx.x, lane = tid & 31, w = tid >> 5;
    int wm = (w & 1) * 64, wn = (w >> 1) * 32;
    int m0 = blockIdx.y * 128, n0 = blockIdx.x * 128;

    float acc[4][4][4];
    #pragma unroll
    for (int i = 0; i < 4; i++)
        #pragma unroll
        for (int j = 0; j < 4; j++)
            #pragma unroll
            for (int r = 0; r < 4; r++) acc[i][j][r] = 0.f;

    const int nch = K >> 5;
    const int row = tid >> 2, seg = tid & 3;

    auto stage = [&](int kc, int s) {
        uint32_t base = sbase + (uint32_t)s * 2 * TBUF * 2;
        const size_t ka = (size_t)kc * 32;
        #pragma unroll
        for (int it = 0; it < 2; it++) {
            int r = row + it * 64;
            uint32_t so = (uint32_t)r * 80 + seg * 16;
            cp16(base + so,            Ap + (size_t)(m0 + r) * K + ka + seg * 8);
            cp16(base + TBUF * 2 + so, Bp + (size_t)(n0 + r) * K + ka + seg * 8);
        }
    };

    stage(0, 0);
    cp_commit();

    for (int kc = 0; kc < nch; kc++) {
        if (kc + 1 < nch) {
            stage(kc + 1, (kc + 1) & 1);
            cp_commit();
            asm volatile("cp.async.wait_group 1;" ::: "memory");
        } else {
            asm volatile("cp.async.wait_group 0;" ::: "memory");
        }
        __syncthreads();

        uint32_t base = sbase + (uint32_t)(kc & 1) * 2 * TBUF * 2;
        uint32_t bA = base, bB = base + TBUF * 2;

        #pragma unroll
        for (int ks = 0; ks < 2; ks++) {
            int arow = wm + (lane & 15);
            int akk  = ks * 16 + (lane >> 4) * 8;
            uint32_t aoff = (uint32_t)(arow * AST + akk) * 2;

            uint32_t a[4][4], bq[4][2];
            #pragma unroll
            for (int mi = 0; mi < 4; mi++)
                ldsm4(a[mi][0], a[mi][1], a[mi][2], a[mi][3],
                      bA + aoff + mi * 16 * AST * 2);
            int brow = wn + (lane & 15);
            uint32_t boff0 = (uint32_t)(brow * AST + akk) * 2;
            #pragma unroll
            for (int nb = 0; nb < 2; nb++) {
                uint32_t r0, r1, r2, r3;
                ldsm4(r0, r1, r2, r3, bB + boff0 + nb * 16 * AST * 2);
                bq[nb * 2 + 0][0] = r0; bq[nb * 2 + 0][1] = r2;
                bq[nb * 2 + 1][0] = r1; bq[nb * 2 + 1][1] = r3;
            }
            #pragma unroll
            for (int mi = 0; mi < 4; mi++)
                #pragma unroll
                for (int ni = 0; ni < 4; ni++)
                    mma_f16(acc[mi][ni], a[mi], bq[ni]);
        }
        __syncthreads();
    }

    #pragma unroll
    for (int mi = 0; mi < 4; mi++) {
        #pragma unroll
        for (int ni = 0; ni < 4; ni++) {
            int r = m0 + wm + mi * 16 + (lane >> 2);
            int c = n0 + wn + ni * 8 + (lane & 3) * 2;
            float b0 = 0.f, b1 = 0.f;
            if (bias) { b0 = bias[c]; b1 = bias[c + 1]; }
            #pragma unroll
            for (int half = 0; half < 2; half++) {
                int rr = r + half * 8;
                float v0 = acc[mi][ni][half * 2 + 0] + b0;
                float v1 = acc[mi][ni][half * 2 + 1] + b1;
                if (res) {
                    float2 rv = *(const float2*)(res + (size_t)rr * N + c);
                    v0 += rv.x; v1 += rv.y;
                }
                if (relu) { v0 = fmaxf(v0, 0.f); v1 = fmaxf(v1, 0.f); }
                if (Cf)
                    *(float2*)(Cf + (size_t)rr * N + c) = make_float2(v0, v1);
                if (Oh)
                    *(uint32_t*)(Oh + (size_t)rr * N + c) = pack_f16x2(v0, v1);
            }
        }
    }
}

// ---------------------------------------------------------------------------
// Fused flash attention (fp16 HMMA, online softmax). Writes fp16.
// 64 Q rows, 128 threads, 4 warps; cp.async double-buffered K/V staging.
// Q, K, V read DIRECTLY from head-interleaved GEMM outputs.
// V staged [s][d], consumed via ldmatrix.trans.
// ---------------------------------------------------------------------------
__global__ __launch_bounds__(128) void flash_kernel(
    const __half* __restrict__ Qb, int qStride, int qOff,
    const __half* __restrict__ Kb, int kStride, int kOff,
    const __half* __restrict__ Vb, int vStride, int vOff,
    __half* __restrict__ Oh, int Tq, int Tk, float qscale, int causal)
{
    constexpr int ST = 72;               // halves; row = 144 B = 9 x 16 B
    constexpr int KVB = 64 * ST;         // halves per K/V buffer
    __shared__ __half sQ[64 * ST];
    __shared__ __half sK[2 * KVB];
    __shared__ __half sV[2 * KVB];
    uint32_t bQ = smem_u32(sQ), bK0 = smem_u32(sK), bV0 = smem_u32(sV);

    int tid = threadIdx.x, lane = tid & 31, w = tid >> 5;
    int qt = blockIdx.x, bh = blockIdx.y;
    int b = bh >> 4, h = bh & 15;
    int q0 = qt * 64;

    auto stageKV = [&](int kt, int s) {
        const __half* Kp = Kb + (size_t)(b * 448 + kt * 64) * kStride + kOff + h * 64;
        const __half* Vp = Vb + (size_t)(b * 448 + kt * 64) * vStride + vOff + h * 64;
        uint32_t kb = bK0 + (uint32_t)s * KVB * 2;
        uint32_t vb = bV0 + (uint32_t)s * KVB * 2;
        #pragma unroll
        for (int it = 0; it < 4; it++) {
            int idx = tid + it * 128;
            int row = idx >> 3, c8 = (idx & 7) * 8;
            uint32_t so = (uint32_t)(row * ST + c8) * 2;
            cp16(kb + so, Kp + (size_t)row * kStride + c8);
            cp16(vb + so, Vp + (size_t)row * vStride + c8);
        }
    };

    const __half* Qp = Qb + (size_t)(b * 448 + q0) * qStride + qOff + h * 64;
    #pragma unroll
    for (int it = 0; it < 4; it++) {
        int idx = tid + it * 128;
        int row = idx >> 3, c8 = (idx & 7) * 8;
        *(uint4*)&sQ[row * ST + c8] = *(const uint4*)(Qp + (size_t)row * qStride + c8);
    }

    stageKV(0, 0);
    cp_commit();
    __syncthreads();

    uint32_t qf[4][4];
    {
        int r = w * 16 + (lane & 15);
        #pragma unroll
        for (int ks = 0; ks < 4; ks++) {
            uint32_t addr = bQ + (uint32_t)(r * ST + ks * 16 + (lane >> 4) * 8) * 2;
            ldsm4(qf[ks][0], qf[ks][1], qf[ks][2], qf[ks][3], addr);
        }
    }

    float m[2] = {-1e30f, -1e30f}, l[2] = {0.f, 0.f};
    float o[8][4];
    #pragma unroll
    for (int i = 0; i < 8; i++)
        #pragma unroll
        for (int j = 0; j < 4; j++) o[i][j] = 0.f;

    int r0g = q0 + w * 16 + (lane >> 2);

    int nkt = causal ? (qt + 1) : (Tk >> 6);
    for (int kt = 0; kt < nkt; kt++) {
        if (kt + 1 < nkt) {
            stageKV(kt + 1, (kt + 1) & 1);
            cp_commit();
            asm volatile("cp.async.wait_group 1;" ::: "memory");
        } else {
            asm volatile("cp.async.wait_group 0;" ::: "memory");
        }
        __syncthreads();

        uint32_t bK = bK0 + (uint32_t)(kt & 1) * KVB * 2;
        uint32_t bV = bV0 + (uint32_t)(kt & 1) * KVB * 2;

        float s_acc[8][4];
        #pragma unroll
        for (int i = 0; i < 8; i++)
            #pragma unroll
            for (int j = 0; j < 4; j++) s_acc[i][j] = 0.f;

        #pragma unroll
        for (int ng = 0; ng < 4; ng++) {
            int nrow = ng * 16 + (lane & 15);
            #pragma unroll
            for (int ks = 0; ks < 4; ks++) {
                uint32_t r0, r1, r2, r3;
                ldsm4(r0, r1, r2, r3,
                      bK + (uint32_t)(nrow * ST + ks * 16 + (lane >> 4) * 8) * 2);
                uint32_t b0[2] = {r0, r2}, b1[2] = {r1, r3};
                mma_f16(s_acc[ng * 2 + 0], qf[ks], b0);
                mma_f16(s_acc[ng * 2 + 1], qf[ks], b1);
            }
        }

        #pragma unroll
        for (int i = 0; i < 8; i++)
            #pragma unroll
            for (int j = 0; j < 4; j++) s_acc[i][j] *= qscale;

        if (causal && kt == qt) {
            #pragma unroll
            for (int nb = 0; nb < 8; nb++) {
                int cg = kt * 64 + nb * 8 + (lane & 3) * 2;
                #pragma unroll
                for (int half = 0; half < 2; half++) {
                    int rg = r0g + half * 8;
                    if (cg > rg)     s_acc[nb][half * 2 + 0] = -1e30f;
                    if (cg + 1 > rg) s_acc[nb][half * 2 + 1] = -1e30f;
                }
            }
        }

        float tmax[2] = {-1e30f, -1e30f};
        #pragma unroll
        for (int nb = 0; nb < 8; nb++) {
            tmax[0] = fmaxf(tmax[0], fmaxf(s_acc[nb][0], s_acc[nb][1]));
            tmax[1] = fmaxf(tmax[1], fmaxf(s_acc[nb][2], s_acc[nb][3]));
        }
        #pragma unroll
        for (int i = 0; i < 2; i++) {
            tmax[i] = fmaxf(tmax[i], __shfl_xor_sync(0xffffffffu, tmax[i], 1));
            tmax[i] = fmaxf(tmax[i], __shfl_xor_sync(0xffffffffu, tmax[i], 2));
        }
        float mn[2] = {fmaxf(m[0], tmax[0]), fmaxf(m[1], tmax[1])};
        float fac[2] = {__expf(m[0] - mn[0]), __expf(m[1] - mn[1])};
        m[0] = mn[0]; m[1] = mn[1];

        uint32_t pf[4][4];
        float rs[2] = {0.f, 0.f};
        #pragma unroll
        for (int nb = 0; nb < 8; nb++) {
            float e0 = __expf(s_acc[nb][0] - mn[0]);
            float e1 = __expf(s_acc[nb][1] - mn[0]);
            float e2 = __expf(s_acc[nb][2] - mn[1]);
            float e3 = __expf(s_acc[nb][3] - mn[1]);
            rs[0] += e0 + e1;
            rs[1] += e2 + e3;
            pf[nb >> 1][(nb & 1) * 2 + 0] = pack_f16x2(e0, e1);
            pf[nb >> 1][(nb & 1) * 2 + 1] = pack_f16x2(e2, e3);
        }
        #pragma unroll
        for (int i = 0; i < 2; i++) {
            rs[i] += __shfl_xor_sync(0xffffffffu, rs[i], 1);
            rs[i] += __shfl_xor_sync(0xffffffffu, rs[i], 2);
        }
        l[0] = l[0] * fac[0] + rs[0];
        l[1] = l[1] * fac[1] + rs[1];
        #pragma unroll
        for (int nb = 0; nb < 8; nb++) {
            o[nb][0] *= fac[0]; o[nb][1] *= fac[0];
            o[nb][2] *= fac[1]; o[nb][3] *= fac[1];
        }

        #pragma unroll
        for (int ng = 0; ng < 4; ng++) {
            #pragma unroll
            for (int ks = 0; ks < 4; ks++) {
                uint32_t t0, t1, t2, t3;
                ldsm4_t(t0, t1, t2, t3,
                        bV + (uint32_t)((ks * 16 + (lane & 15)) * ST
                                        + ng * 16 + (lane >> 4) * 8) * 2);
                uint32_t b0[2] = {t0, t1}, b1[2] = {t2, t3};
                mma_f16(o[ng * 2 + 0], pf[ks], b0);
                mma_f16(o[ng * 2 + 1], pf[ks], b1);
            }
        }
        __syncthreads();
    }

    float inv0 = 1.f / l[0], inv1 = 1.f / l[1];
    #pragma unroll
    for (int nb = 0; nb < 8; nb++) {
        int col = h * 64 + nb * 8 + (lane & 3) * 2;
        #pragma unroll
        for (int half = 0; half < 2; half++) {
            float inv = half ? inv1 : inv0;
            float v0 = o[nb][half * 2 + 0] * inv;
            float v1 = o[nb][half * 2 + 1] * inv;
            size_t off = ((size_t)b * Tq + r0g + half * 8) * C + col;
            *(uint32_t*)(Oh + off) = pack_f16x2(v0, v1);
        }
    }
}

// ---------------------------------------------------------------------------
// LayerNorm: one block per row, writes fp16
// ---------------------------------------------------------------------------
__inline__ __device__ float warp_sum(float v) {
    #pragma unroll
    for (int o = 16; o > 0; o >>= 1) v += __shfl_xor_sync(0xffffffffu, v, o);
    return v;
}

__global__ __launch_bounds__(256) void ln_kernel(
    const float* __restrict__ x, const float* __restrict__ g,
    const float* __restrict__ b, __half* __restrict__ oh)
{
    __shared__ float s_sum[8], s_sq[8];
    int tid = threadIdx.x;
    const float* xr = x + (size_t)blockIdx.x * C;
    float s = 0.f, s2 = 0.f;
    for (int i = tid; i < C; i += 256) { float v = xr[i]; s += v; s2 += v * v; }
    s = warp_sum(s); s2 = warp_sum(s2);
    if ((tid & 31) == 0) { s_sum[tid >> 5] = s; s_sq[tid >> 5] = s2; }
    __syncthreads();
    if (tid < 32) {
        float a  = tid < 8 ? s_sum[tid] : 0.f;
        float c2 = tid < 8 ? s_sq[tid]  : 0.f;
        a = warp_sum(a); c2 = warp_sum(c2);
        if (tid == 0) { s_sum[0] = a; s_sq[0] = c2; }
    }
    __syncthreads();
    float mean = s_sum[0] * (1.f / C);
    float var  = s_sq[0] * (1.f / C) - mean * mean;
    float rstd = rsqrtf(var + 1e-5f);
    size_t base = (size_t)blockIdx.x * C;
    for (int i = tid; i < C; i += 256) {
        float v = (xr[i] - mean) * rstd * g[i] + b[i];
        oh[base + i] = __float2half_rn(v);
    }
}

// ---------------------------------------------------------------------------
// Launch: full decoder block, 3-stream DAG
// ---------------------------------------------------------------------------
extern "C" void kernel_launch(void* const* d_in, const int* in_sizes, int n_in,
                              void* d_out, int out_size)
{
    (void)in_sizes; (void)n_in; (void)out_size;
    const float* tgt      = (const float*)d_in[0];
    const float* src      = (const float*)d_in[1];
    const float* sa_wqkv  = (const float*)d_in[2];
    const float* sa_wproj = (const float*)d_in[3];
    const float* sa_bproj = (const float*)d_in[4];
    const float* ed_wkv   = (const float*)d_in[5];
    const float* ed_wq    = (const float*)d_in[6];
    const float* ed_wproj = (const float*)d_in[7];
    const float* ed_bproj = (const float*)d_in[8];
    const float* ff_w1    = (const float*)d_in[9];
    const float* ff_b1    = (const float*)d_in[10];
    const float* ff_w2    = (const float*)d_in[11];
    const float* ff_b2    = (const float*)d_in[12];
    const float* ln1_g    = (const float*)d_in[13];
    const float* ln1_b    = (const float*)d_in[14];
    const float* ln2_g    = (const float*)d_in[15];
    const float* ln2_b    = (const float*)d_in[16];
    const float* ln3_g    = (const float*)d_in[17];
    const float* ln3_b    = (const float*)d_in[18];
    float* out = (float*)d_out;

    static __half *ln1p = nullptr, *ln2p, *ln3p, *op, *hid, *wt;
    static __half *x1, *x2, *x3;
    static cudaStream_t sA = nullptr, sB = nullptr;
    static cudaEvent_t e0 = nullptr, eKV = nullptr, eF1 = nullptr, eW = nullptr;
    if (!ln1p) {
        cudaGetSymbolAddress((void**)&ln1p, g_ln1);
        cudaGetSymbolAddress((void**)&ln2p, g_ln2);
        cudaGetSymbolAddress((void**)&ln3p, g_ln3);
        cudaGetSymbolAddress((void**)&op,   g_o);
        cudaGetSymbolAddress((void**)&hid,  g_hid);
        cudaGetSymbolAddress((void**)&wt,   g_wt);
        cudaGetSymbolAddress((void**)&x1,   g_x1);
        cudaGetSymbolAddress((void**)&x2,   g_x2);
        cudaGetSymbolAddress((void**)&x3,   g_x3);
        cudaStreamCreateWithFlags(&sA, cudaStreamNonBlocking);
        cudaStreamCreateWithFlags(&sB, cudaStreamNonBlocking);
        cudaEventCreateWithFlags(&e0,  cudaEventDisableTiming);
        cudaEventCreateWithFlags(&eKV, cudaEventDisableTiming);
        cudaEventCreateWithFlags(&eF1, cudaEventDisableTiming);
        cudaEventCreateWithFlags(&eW,  cudaEventDisableTiming);
    }

    const float scale = 0.03125f;   // C^-0.5

    const size_t o_qkv = 0, o_sap = 3 * C2, o_kv = 4 * C2, o_q = 6 * C2,
                 o_edp = 7 * C2, o_f1 = 8 * C2, o_f2 = 12 * C2;

    // ---- fork ----
    cudaEventRecord(e0, 0);
    cudaStreamWaitEvent(sA, e0, 0);
    cudaStreamWaitEvent(sB, e0, 0);

    // ---- branch A (stream sA): cross-attention K/V from src ----
    wconv_kernel<<<dim3(2 * C / 32, C / 32), 256, 0, sA>>>(ed_wkv, wt + o_kv, C, 2 * C);
    ln_kernel<<<B * J, 256, 0, sA>>>(src, ln2_g, ln2_b, ln2p);
    hmma_gemm<<<dim3(2 * C / 128, (B * J) / 128), 256, 0, sA>>>(
        ln2p, wt + o_kv, nullptr, nullptr, nullptr, x2, B * J, 2 * C, C, 0);
    cudaEventRecord(eKV, sA);

    // ---- branch B (stream sB): late-needed weights first, then FFN hidden ----
    wconv_kernel<<<dim3(C / 32, C / 32), 256, 0, sB>>>(sa_wproj, wt + o_sap, C, C);
    wconv_kernel<<<dim3(C / 32, C / 32), 256, 0, sB>>>(ed_wq,    wt + o_q,   C, C);
    wconv_kernel<<<dim3(C / 32, C / 32), 256, 0, sB>>>(ed_wproj, wt + o_edp, C, C);
    cudaEventRecord(eW, sB);
    wconv_kernel<<<dim3(4 * C / 32, C / 32), 256, 0, sB>>>(ff_w1, wt + o_f1, C, 4 * C);
    wconv_kernel<<<dim3(C / 32, 4 * C / 32), 256, 0, sB>>>(ff_w2, wt + o_f2, 4 * C, C);
    ln_kernel<<<ROWS, 256, 0, sB>>>(tgt, ln3_g, ln3_b, ln3p);
    hmma_gemm<<<dim3(4 * C / 128, ROWS / 128), 256, 0, sB>>>(
        ln3p, wt + o_f1, ff_b1, nullptr, nullptr, hid, ROWS, 4 * C, C, 1);
    cudaEventRecord(eF1, sB);

    // ---- origin stream: critical path (only qkv weights + ln1 gate it) ----
    wconv_kernel<<<dim3(3 * C / 32, C / 32), 256>>>(sa_wqkv, wt + o_qkv, C, 3 * C);
    ln_kernel<<<ROWS, 256>>>(tgt, ln1_g, ln1_b, ln1p);
    hmma_gemm<<<dim3(3 * C / 128, ROWS / 128), 256>>>(
        ln1p, wt + o_qkv, nullptr, nullptr, nullptr, x1, ROWS, 3 * C, C, 0);
    flash_kernel<<<dim3(T / 64, B * H), 128>>>(
        x1, 3 * C, 0, x1, 3 * C, C, x1, 3 * C, 2 * C, op, T, T, scale, 1);
    cudaStreamWaitEvent(0, eW, 0);       // sa_wproj/ed_wq/ed_wproj ready (long since)
    hmma_gemm<<<dim3(C / 128, ROWS / 128), 256>>>(
        op, wt + o_sap, sa_bproj, tgt, out, nullptr, ROWS, C, C, 0);
    ln_kernel<<<ROWS, 256>>>(out, ln2_g, ln2_b, ln1p);
    hmma_gemm<<<dim3(C / 128, ROWS / 128), 256>>>(
        ln1p, wt + o_q, nullptr, nullptr, nullptr, x3, ROWS, C, C, 0);

    cudaStreamWaitEvent(0, eKV, 0);      // join branch A
    flash_kernel<<<dim3(T / 64, B * H), 128>>>(
        x3, C, 0, x2, 2 * C, 0, x2, 2 * C, C, op, T, J, scale, 0);
    hmma_gemm<<<dim3(C / 128, ROWS / 128), 256>>>(
        op, wt + o_edp, ed_bproj, out, out, nullptr, ROWS, C, C, 0);

    cudaStreamWaitEvent(0, eF1, 0);      // join branch B
    hmma_gemm<<<dim3(C / 128, ROWS / 128), 256>>>(
        hid, wt + o_f2, ff_b2, out, out, nullptr, ROWS, C, 4 * C, 0);
}